// round 1
// baseline (speedup 1.0000x reference)
#include <cuda_runtime.h>
#include <math.h>

#define NB 32
#define NA 5
#define NC 80
#define NH 38
#define NW 38
#define MAXT 50
#define NCELL (NH*NW)          // 1444
#define CH_PER_A (5 + NC)      // 85
#define SIL_THRESH 0.6f
#define OBJECT_SCALE 5.0f

__constant__ float c_anchors[2*NA] = {
    1.3221f, 1.73145f, 3.19275f, 4.00944f, 5.05587f,
    8.09892f, 9.47112f, 4.84053f, 11.2364f, 10.0071f
};

// scratch (no allocations allowed)
__device__ double g_acc;
__device__ float  g_gx[NB*MAXT], g_gy[NB*MAXT], g_gw[NB*MAXT], g_gh[NB*MAXT];
__device__ float  g_txv[NB*MAXT], g_tyv[NB*MAXT], g_twv[NB*MAXT], g_thv[NB*MAXT];
__device__ int    g_bn[NB*MAXT], g_gi[NB*MAXT], g_gj[NB*MAXT], g_cls[NB*MAXT];
__device__ int    g_nvalid[NB];

__device__ __forceinline__ float bbox_iou(float ax, float ay, float aw, float ah,
                                          float bx, float by, float bw, float bh) {
    float mx = fminf(ax - aw*0.5f, bx - bw*0.5f);
    float Mx = fmaxf(ax + aw*0.5f, bx + bw*0.5f);
    float my = fminf(ay - ah*0.5f, by - bh*0.5f);
    float My = fmaxf(ay + ah*0.5f, by + bh*0.5f);
    float cw = aw + bw - (Mx - mx);
    float ch = ah + bh - (My - my);
    float inter = (cw > 0.0f && ch > 0.0f) ? cw*ch : 0.0f;
    float uni = aw*ah + bw*bh - inter;
    return inter / fmaxf(uni, 1e-12f);
}

__global__ void zero_k() { g_acc = 0.0; }

// one block per batch, 64 threads (50 active)
__global__ void prep_k(const float* __restrict__ target) {
    int b = blockIdx.x;
    int t = threadIdx.x;
    __shared__ int nz[MAXT];
    if (t < MAXT)
        nz[t] = (target[b*MAXT*5 + t*5 + 1] != 0.0f) ? 1 : 0;
    __syncthreads();
    if (t == 0) {
        int nv = 0;
        while (nv < MAXT && nz[nv]) nv++;
        g_nvalid[b] = nv;
    }
    if (t >= MAXT) return;

    const float* tg = target + b*MAXT*5 + t*5;
    float gx = tg[1] * (float)NW;
    float gy = tg[2] * (float)NH;
    float gw = tg[3] * (float)NW;
    float gh = tg[4] * (float)NH;

    // best anchor by wh-only IoU (argmax, first max wins)
    float best = -1.0f; int bn = 0;
    #pragma unroll
    for (int a = 0; a < NA; a++) {
        float iou = bbox_iou(0.f, 0.f, gw, gh, 0.f, 0.f, c_anchors[2*a], c_anchors[2*a+1]);
        if (iou > best) { best = iou; bn = a; }
    }
    int gi = min(max((int)floorf(gx), 0), NW-1);
    int gj = min(max((int)floorf(gy), 0), NH-1);

    int idx = b*MAXT + t;
    g_gx[idx] = gx;  g_gy[idx] = gy;  g_gw[idx] = gw;  g_gh[idx] = gh;
    g_txv[idx] = gx - (float)gi;
    g_tyv[idx] = gy - (float)gj;
    g_twv[idx] = logf(fmaxf(gw, 1e-12f) / c_anchors[2*bn]);
    g_thv[idx] = logf(fmaxf(gh, 1e-12f) / c_anchors[2*bn+1]);
    g_bn[idx] = bn;  g_gi[idx] = gi;  g_gj[idx] = gj;
    g_cls[idx] = (int)tg[0];
}

// grid: (ceil(1444/256), NB*NA), block 256
__global__ void loss_k(const float* __restrict__ out) {
    int ba = blockIdx.y;
    int b = ba / NA;
    int a = ba % NA;
    int tid = threadIdx.x;

    __shared__ float s_gx[MAXT], s_gy[MAXT], s_gw[MAXT], s_gh[MAXT];
    __shared__ float s_tx[MAXT], s_ty[MAXT], s_tw[MAXT], s_th[MAXT];
    __shared__ int   s_bn[MAXT], s_gi[MAXT], s_gj[MAXT], s_cls[MAXT];
    __shared__ int   s_nv;
    __shared__ float s_warp[8];

    if (tid < MAXT) {
        int idx = b*MAXT + tid;
        s_gx[tid] = g_gx[idx];  s_gy[tid] = g_gy[idx];
        s_gw[tid] = g_gw[idx];  s_gh[tid] = g_gh[idx];
        s_tx[tid] = g_txv[idx]; s_ty[tid] = g_tyv[idx];
        s_tw[tid] = g_twv[idx]; s_th[tid] = g_thv[idx];
        s_bn[tid] = g_bn[idx];  s_gi[tid] = g_gi[idx];
        s_gj[tid] = g_gj[idx];  s_cls[tid] = g_cls[idx];
    }
    if (tid == 0) s_nv = g_nvalid[b];
    __syncthreads();

    int cell = blockIdx.x * blockDim.x + tid;
    float lacc = 0.0f;

    if (cell < NCELL) {
        int j = cell / NW;
        int i = cell % NW;
        const float* p = out + (b*NA + a) * CH_PER_A * NCELL + cell;
        float xr = p[0];
        float yr = p[1*NCELL];
        float wr = p[2*NCELL];
        float hr = p[3*NCELL];
        float cr = p[4*NCELL];

        float x    = 1.0f / (1.0f + expf(-xr));
        float y    = 1.0f / (1.0f + expf(-yr));
        float conf = 1.0f / (1.0f + expf(-cr));

        float aw = c_anchors[2*a], ah = c_anchors[2*a+1];
        float px = x + (float)i;
        float py = y + (float)j;
        float pw = expf(wr) * aw;
        float ph = expf(hr) * ah;

        float maxiou = 0.0f;
        float txv = 0.5f, tyv = 0.5f, twv = 0.0f, thv = 0.0f, tconf = 0.0f;
        int tcls = 0, matched = 0;

        int nv = s_nv;
        for (int t = 0; t < nv; t++) {
            float iou = bbox_iou(s_gx[t], s_gy[t], s_gw[t], s_gh[t], px, py, pw, ph);
            maxiou = fmaxf(maxiou, iou);
            if (s_bn[t] == a && s_gi[t] == i && s_gj[t] == j) {
                matched = 1;
                txv = s_tx[t]; tyv = s_ty[t];
                twv = s_tw[t]; thv = s_th[t];
                tconf = iou;   tcls = s_cls[t];
            }
        }

        float cm2 = matched ? OBJECT_SCALE : (maxiou > SIL_THRESH ? 0.0f : 1.0f);
        float dx = x - txv, dy = y - tyv;
        float dw = wr - twv, dh = hr - thv;
        float dc = conf - tconf;
        lacc = 0.5f * (dx*dx + dy*dy + dw*dw + dh*dh + cm2*dc*dc);

        if (matched) {
            const float* cp = p + 5*NCELL;
            float m = -3.4e38f;
            for (int c = 0; c < NC; c++) m = fmaxf(m, cp[c*NCELL]);
            float se = 0.0f;
            for (int c = 0; c < NC; c++) se += expf(cp[c*NCELL] - m);
            float logp = cp[tcls*NCELL] - m - logf(se);
            lacc -= logp;   // cls_mask = 1, CLASS_SCALE = 1
        }
    }

    // block reduction
    #pragma unroll
    for (int o = 16; o > 0; o >>= 1)
        lacc += __shfl_down_sync(0xffffffff, lacc, o);
    if ((tid & 31) == 0) s_warp[tid >> 5] = lacc;
    __syncthreads();
    if (tid == 0) {
        double s = 0.0;
        #pragma unroll
        for (int w = 0; w < 8; w++) s += (double)s_warp[w];
        atomicAdd(&g_acc, s);
    }
}

__global__ void fin_k(float* o) { o[0] = (float)g_acc; }

extern "C" void kernel_launch(void* const* d_in, const int* in_sizes, int n_in,
                              void* d_out, int out_size) {
    const float* output = (const float*)d_in[0];
    const float* target = (const float*)d_in[1];
    // d_in[2] = features: unused by the reference loss

    zero_k<<<1, 1>>>();
    prep_k<<<NB, 64>>>(target);
    dim3 grid((NCELL + 255) / 256, NB * NA);
    loss_k<<<grid, 256>>>(output);
    fin_k<<<1, 1>>>((float*)d_out);
}

// round 2
// speedup vs baseline: 1.3500x; 1.3500x over previous
#include <cuda_runtime.h>
#include <math.h>

#define NB 32
#define NA 5
#define NC 80
#define NH 38
#define NW 38
#define MAXT 50
#define NCELL (NH*NW)          // 1444
#define HALFCELL 722
#define CH_PER_A (5 + NC)      // 85
#define OBJECT_SCALE 5.0f
#define GRIDX 2
#define TOTAL_BLOCKS (GRIDX * NB * NA)   // 320

__constant__ float c_anchors[2*NA] = {
    1.3221f, 1.73145f, 3.19275f, 4.00944f, 5.05587f,
    8.09892f, 9.47112f, 4.84053f, 11.2364f, 10.0071f
};

__device__ double g_acc = 0.0;
__device__ unsigned int g_count = 0;

__device__ __forceinline__ float wh_iou(float gw, float gh, float aw, float ah) {
    // center-format IoU of (0,0,gw,gh) vs (0,0,aw,ah)
    float Mx = fmaxf(gw, aw) * 0.5f;
    float mx = -Mx;
    float My = fmaxf(gh, ah) * 0.5f;
    float my = -My;
    float cw = gw + aw - (Mx - mx);
    float ch = gh + ah - (My - my);
    float inter = (cw > 0.0f && ch > 0.0f) ? cw*ch : 0.0f;
    float uni = gw*gh + aw*ah - inter;
    return inter / fmaxf(uni, 1e-12f);
}

__global__ void __launch_bounds__(256, 4)
region_loss_k(const float* __restrict__ out, const float* __restrict__ target,
              float* __restrict__ res) {
    int ba = blockIdx.y;
    int b = ba / NA;
    int a = ba % NA;
    int tid = threadIdx.x;

    // per-target precomputed data (redundant per block; trivial)
    __shared__ float4 s_b0[MAXT];   // gl, gr, gtop, gbot
    __shared__ float4 s_b1[MAXT];   // gw, gh, gwh, key(int bits)
    __shared__ float4 s_tv[MAXT];   // tx, ty, tw, th
    __shared__ int    s_cls[MAXT];
    __shared__ int    s_flag[MAXT];
    __shared__ int    s_nv;
    __shared__ float  s_warp[8];

    if (tid < MAXT) {
        const float* tg = target + b*MAXT*5 + tid*5;
        float t0 = tg[0], t1 = tg[1], t2 = tg[2], t3 = tg[3], t4 = tg[4];
        s_flag[tid] = (t1 != 0.0f) ? 1 : 0;
        float gx = t1 * (float)NW;
        float gy = t2 * (float)NH;
        float gw = t3 * (float)NW;
        float gh = t4 * (float)NH;

        // best anchor by wh-only IoU (first max wins)
        float best = -1.0f; int bn = 0;
        #pragma unroll
        for (int an = 0; an < NA; an++) {
            float iou = wh_iou(gw, gh, c_anchors[2*an], c_anchors[2*an+1]);
            if (iou > best) { best = iou; bn = an; }
        }
        int gi = min(max((int)floorf(gx), 0), NW-1);
        int gj = min(max((int)floorf(gy), 0), NH-1);

        float hw = gw * 0.5f, hh = gh * 0.5f;
        int key = (bn << 12) | (gj << 6) | gi;
        s_b0[tid] = make_float4(gx - hw, gx + hw, gy - hh, gy + hh);
        s_b1[tid] = make_float4(gw, gh, gw*gh, __int_as_float(key));
        s_tv[tid] = make_float4(gx - (float)gi, gy - (float)gj,
                                __logf(fmaxf(gw, 1e-12f) / c_anchors[2*bn]),
                                __logf(fmaxf(gh, 1e-12f) / c_anchors[2*bn+1]));
        s_cls[tid] = (int)t0;
    }
    __syncthreads();
    if (tid == 0) {
        int nv = 0;
        while (nv < MAXT && s_flag[nv]) nv++;
        s_nv = nv;
    }
    __syncthreads();
    int nv = s_nv;

    float aw = c_anchors[2*a], ah = c_anchors[2*a+1];
    const float* base = out + (size_t)(b*NA + a) * CH_PER_A * NCELL;

    float lacc = 0.0f;
    int cell0 = blockIdx.x * HALFCELL;

    for (int c0 = tid; c0 < HALFCELL; c0 += 256) {
        int cell = cell0 + c0;
        int j = cell / NW;
        int i = cell - j * NW;
        const float* p = base + cell;
        float xr = p[0];
        float yr = p[1*NCELL];
        float wr = p[2*NCELL];
        float hr = p[3*NCELL];
        float cr = p[4*NCELL];

        float x    = __fdividef(1.0f, 1.0f + __expf(-xr));
        float y    = __fdividef(1.0f, 1.0f + __expf(-yr));
        float conf = __fdividef(1.0f, 1.0f + __expf(-cr));

        float px = x + (float)i;
        float py = y + (float)j;
        float pw = __expf(wr) * aw;
        float ph = __expf(hr) * ah;
        float hwp = pw * 0.5f, hhp = ph * 0.5f;
        float pl = px - hwp, pr = px + hwp;
        float pt = py - hhp, pb = py + hhp;
        float pwh = pw * ph;

        int key = (a << 12) | (j << 6) | i;

        float bi = 0.0f, bu = 1.0f;   // best iou as rational inter/union
        int mt = -1;
        for (int t = 0; t < nv; t++) {
            float4 b0 = s_b0[t];
            float4 b1 = s_b1[t];
            float mx = fminf(b0.x, pl);
            float Mx = fmaxf(b0.y, pr);
            float my = fminf(b0.z, pt);
            float My = fmaxf(b0.w, pb);
            float cw = b1.x + pw - (Mx - mx);
            float ch = b1.y + ph - (My - my);
            float inter = (cw > 0.0f && ch > 0.0f) ? cw*ch : 0.0f;
            float u = b1.z + pwh - inter;
            bool better = inter * bu > bi * u;
            bi = better ? inter : bi;
            bu = better ? u : bu;
            if (__float_as_int(b1.w) == key) mt = t;
        }

        float txv = 0.5f, tyv = 0.5f, twv = 0.0f, thv = 0.0f, tconf = 0.0f;
        float cm2;
        if (mt >= 0) {
            // recompute iou for the matched (last-wins) target
            float4 b0 = s_b0[mt];
            float4 b1 = s_b1[mt];
            float mx = fminf(b0.x, pl);
            float Mx = fmaxf(b0.y, pr);
            float my = fminf(b0.z, pt);
            float My = fmaxf(b0.w, pb);
            float cw = b1.x + pw - (Mx - mx);
            float ch = b1.y + ph - (My - my);
            float inter = (cw > 0.0f && ch > 0.0f) ? cw*ch : 0.0f;
            float u = b1.z + pwh - inter;
            tconf = inter / fmaxf(u, 1e-12f);
            float4 tv = s_tv[mt];
            txv = tv.x; tyv = tv.y; twv = tv.z; thv = tv.w;
            cm2 = OBJECT_SCALE;
        } else {
            cm2 = (bi > 0.6f * bu) ? 0.0f : 1.0f;
        }

        float dx = x - txv, dy = y - tyv;
        float dw = wr - twv, dh = hr - thv;
        float dc = conf - tconf;
        lacc += 0.5f * (dx*dx + dy*dy + dw*dw + dh*dh + cm2*dc*dc);

        if (mt >= 0) {
            int tcls = s_cls[mt];
            const float* cp = p + 5*NCELL;
            float m = -3.4e38f;
            #pragma unroll 4
            for (int c = 0; c < NC; c++) m = fmaxf(m, cp[c*NCELL]);
            float se = 0.0f;
            #pragma unroll 4
            for (int c = 0; c < NC; c++) se += __expf(cp[c*NCELL] - m);
            float logp = cp[tcls*NCELL] - m - __logf(se);
            lacc -= logp;
        }
    }

    // block reduction
    #pragma unroll
    for (int o = 16; o > 0; o >>= 1)
        lacc += __shfl_down_sync(0xffffffff, lacc, o);
    if ((tid & 31) == 0) s_warp[tid >> 5] = lacc;
    __syncthreads();
    if (tid == 0) {
        double s = 0.0;
        #pragma unroll
        for (int w = 0; w < 8; w++) s += (double)s_warp[w];
        atomicAdd(&g_acc, s);
        __threadfence();
        unsigned int done = atomicAdd(&g_count, 1u);
        if (done == TOTAL_BLOCKS - 1) {
            res[0] = (float)g_acc;
            g_acc = 0.0;     // reset for next (deterministic) replay
            g_count = 0;
        }
    }
}

extern "C" void kernel_launch(void* const* d_in, const int* in_sizes, int n_in,
                              void* d_out, int out_size) {
    const float* output = (const float*)d_in[0];
    const float* target = (const float*)d_in[1];
    // d_in[2] = features: never used by the reference loss

    dim3 grid(GRIDX, NB * NA);
    region_loss_k<<<grid, 256>>>(output, target, (float*)d_out);
}

// round 3
// speedup vs baseline: 1.7795x; 1.3181x over previous
#include <cuda_runtime.h>
#include <math.h>

#define NB 32
#define NA 5
#define NC 80
#define NH 38
#define NW 38
#define MAXT 50
#define NCELL (NH*NW)          // 1444
#define CH_PER_A (5 + NC)      // 85
#define OBJECT_SCALE 5.0f
#define GRIDX ((NCELL + 255) / 256)        // 6
#define TOTAL_BLOCKS (GRIDX * NB * NA)     // 960

__constant__ float c_anchors[2*NA] = {
    1.3221f, 1.73145f, 3.19275f, 4.00944f, 5.05587f,
    8.09892f, 9.47112f, 4.84053f, 11.2364f, 10.0071f
};

__device__ double g_acc = 0.0;
__device__ unsigned int g_count = 0;

__device__ __forceinline__ float wh_iou(float gw, float gh, float aw, float ah) {
    float Mx = fmaxf(gw, aw);
    float My = fmaxf(gh, ah);
    float cw = gw + aw - Mx;     // (Mx - mx) with mx = -Mx/2 scale folded
    float ch = gh + ah - My;
    float inter = (cw > 0.0f && ch > 0.0f) ? cw*ch : 0.0f;
    float uni = gw*gh + aw*ah - inter;
    return inter / fmaxf(uni, 1e-12f);
}

__global__ void __launch_bounds__(256, 4)
region_loss_k(const float* __restrict__ out, const float* __restrict__ target,
              float* __restrict__ res) {
    int ba = blockIdx.y;
    int b = ba / NA;
    int a = ba % NA;
    int tid = threadIdx.x;

    __shared__ float4 s_b0[MAXT];   // gl, gr, gtop, gbot
    __shared__ float4 s_b1[MAXT];   // gw, gh, gwh, key(int bits)
    __shared__ float4 s_tv[MAXT];   // tx, ty, tw, th
    __shared__ int    s_cls[MAXT];
    __shared__ int    s_flag[MAXT];
    __shared__ int    s_nv;
    __shared__ float  s_warp[8];

    if (tid < MAXT) {
        const float* tg = target + b*MAXT*5 + tid*5;
        float t0 = tg[0], t1 = tg[1], t2 = tg[2], t3 = tg[3], t4 = tg[4];
        s_flag[tid] = (t1 != 0.0f) ? 1 : 0;
        float gx = t1 * (float)NW;
        float gy = t2 * (float)NH;
        float gw = t3 * (float)NW;
        float gh = t4 * (float)NH;

        float best = -1.0f; int bn = 0;
        #pragma unroll
        for (int an = 0; an < NA; an++) {
            float iou = wh_iou(gw, gh, c_anchors[2*an], c_anchors[2*an+1]);
            if (iou > best) { best = iou; bn = an; }
        }
        int gi = min(max((int)floorf(gx), 0), NW-1);
        int gj = min(max((int)floorf(gy), 0), NH-1);

        float hw = gw * 0.5f, hh = gh * 0.5f;
        int key = (bn << 12) | (gj << 6) | gi;
        s_b0[tid] = make_float4(gx - hw, gx + hw, gy - hh, gy + hh);
        s_b1[tid] = make_float4(gw, gh, gw*gh, __int_as_float(key));
        s_tv[tid] = make_float4(gx - (float)gi, gy - (float)gj,
                                __logf(fmaxf(gw, 1e-12f) / c_anchors[2*bn]),
                                __logf(fmaxf(gh, 1e-12f) / c_anchors[2*bn+1]));
        s_cls[tid] = (int)t0;
    }
    __syncthreads();
    if (tid == 0) {
        int nv = 0;
        while (nv < MAXT && s_flag[nv]) nv++;
        s_nv = nv;
    }
    __syncthreads();
    int nv = s_nv;

    float lacc = 0.0f;
    int cell = blockIdx.x * 256 + tid;

    if (cell < NCELL) {
        float aw = c_anchors[2*a], ah = c_anchors[2*a+1];
        const float* base = out + (size_t)(b*NA + a) * CH_PER_A * NCELL;

        int j = cell / NW;
        int i = cell - j * NW;
        const float* p = base + cell;
        float xr = p[0];
        float yr = p[1*NCELL];
        float wr = p[2*NCELL];
        float hr = p[3*NCELL];
        float cr = p[4*NCELL];

        float x    = __fdividef(1.0f, 1.0f + __expf(-xr));
        float y    = __fdividef(1.0f, 1.0f + __expf(-yr));
        float conf = __fdividef(1.0f, 1.0f + __expf(-cr));

        float px = x + (float)i;
        float py = y + (float)j;
        float pw = __expf(wr) * aw;
        float ph = __expf(hr) * ah;
        float hwp = pw * 0.5f, hhp = ph * 0.5f;
        float pl = px - hwp, pr = px + hwp;
        float pt = py - hhp, pb = py + hhp;
        float pwh = pw * ph;

        int key = (a << 12) | (j << 6) | i;

        bool over = false;      // any iou > 0.6 (independent OR, no dep chain)
        int mt = -1;            // last matched target index
        #pragma unroll 2
        for (int t = 0; t < nv; t++) {
            float4 b0 = s_b0[t];
            float4 b1 = s_b1[t];
            float mx = fminf(b0.x, pl);
            float Mx = fmaxf(b0.y, pr);
            float my = fminf(b0.z, pt);
            float My = fmaxf(b0.w, pb);
            float cw = b1.x + pw - (Mx - mx);
            float ch = b1.y + ph - (My - my);
            float inter = (cw > 0.0f && ch > 0.0f) ? cw*ch : 0.0f;
            float u = b1.z + pwh - inter;
            over |= (inter > 0.6f * u);
            if (__float_as_int(b1.w) == key) mt = t;
        }

        float txv = 0.5f, tyv = 0.5f, twv = 0.0f, thv = 0.0f, tconf = 0.0f;
        float cm2;
        if (mt >= 0) {
            float4 b0 = s_b0[mt];
            float4 b1 = s_b1[mt];
            float mx = fminf(b0.x, pl);
            float Mx = fmaxf(b0.y, pr);
            float my = fminf(b0.z, pt);
            float My = fmaxf(b0.w, pb);
            float cw = b1.x + pw - (Mx - mx);
            float ch = b1.y + ph - (My - my);
            float inter = (cw > 0.0f && ch > 0.0f) ? cw*ch : 0.0f;
            float u = b1.z + pwh - inter;
            tconf = inter / fmaxf(u, 1e-12f);
            float4 tv = s_tv[mt];
            txv = tv.x; tyv = tv.y; twv = tv.z; thv = tv.w;
            cm2 = OBJECT_SCALE;
        } else {
            cm2 = over ? 0.0f : 1.0f;
        }

        float dx = x - txv, dy = y - tyv;
        float dw = wr - twv, dh = hr - thv;
        float dc = conf - tconf;
        lacc = 0.5f * (dx*dx + dy*dy + dw*dw + dh*dh + cm2*dc*dc);

        if (mt >= 0) {
            int tcls = s_cls[mt];
            const float* cp = p + 5*NCELL;
            float m = -3.4e38f;
            #pragma unroll 4
            for (int c = 0; c < NC; c++) m = fmaxf(m, cp[c*NCELL]);
            float se = 0.0f;
            #pragma unroll 4
            for (int c = 0; c < NC; c++) se += __expf(cp[c*NCELL] - m);
            float logp = cp[tcls*NCELL] - m - __logf(se);
            lacc -= logp;
        }
    }

    // block reduction
    #pragma unroll
    for (int o = 16; o > 0; o >>= 1)
        lacc += __shfl_down_sync(0xffffffff, lacc, o);
    if ((tid & 31) == 0) s_warp[tid >> 5] = lacc;
    __syncthreads();
    if (tid == 0) {
        double s = 0.0;
        #pragma unroll
        for (int w = 0; w < 8; w++) s += (double)s_warp[w];
        atomicAdd(&g_acc, s);
        __threadfence();
        unsigned int done = atomicAdd(&g_count, 1u);
        if (done == TOTAL_BLOCKS - 1) {
            res[0] = (float)g_acc;
            g_acc = 0.0;
            g_count = 0;
        }
    }
}

extern "C" void kernel_launch(void* const* d_in, const int* in_sizes, int n_in,
                              void* d_out, int out_size) {
    const float* output = (const float*)d_in[0];
    const float* target = (const float*)d_in[1];
    // d_in[2] = features: never read by the reference loss

    dim3 grid(GRIDX, NB * NA);
    region_loss_k<<<grid, 256>>>(output, target, (float*)d_out);
}

// round 4
// speedup vs baseline: 1.7959x; 1.0092x over previous
#include <cuda_runtime.h>
#include <math.h>

#define NB 32
#define NA 5
#define NC 80
#define NH 38
#define NW 38
#define MAXT 50
#define NCELL (NH*NW)          // 1444
#define CH_PER_A (5 + NC)      // 85
#define OBJECT_SCALE 5.0f
#define CELLS_PER_BLOCK 512
#define GRIDX ((NCELL + CELLS_PER_BLOCK - 1) / CELLS_PER_BLOCK)   // 3
#define TOTAL_BLOCKS (GRIDX * NB * NA)                            // 480

__constant__ float c_anchors[2*NA] = {
    1.3221f, 1.73145f, 3.19275f, 4.00944f, 5.05587f,
    8.09892f, 9.47112f, 4.84053f, 11.2364f, 10.0071f
};

__device__ double g_acc = 0.0;
__device__ unsigned int g_count = 0;

__device__ __forceinline__ float wh_iou(float gw, float gh, float aw, float ah) {
    float cw = gw + aw - fmaxf(gw, aw);
    float ch = gh + ah - fmaxf(gh, ah);
    float inter = (cw > 0.0f && ch > 0.0f) ? cw*ch : 0.0f;
    float uni = gw*gh + aw*ah - inter;
    return inter / fmaxf(uni, 1e-12f);
}

__global__ void __launch_bounds__(256, 4)
region_loss_k(const float* __restrict__ out, const float* __restrict__ target,
              float* __restrict__ res) {
    int ba = blockIdx.y;
    int b = ba / NA;
    int a = ba % NA;
    int tid = threadIdx.x;

    __shared__ float4 s_bnd[MAXT];   // gl, gt, gr, gb
    __shared__ float2 s_mk[MAXT];    // 0.375*gArea, key(int bits)
    __shared__ float4 s_tv[MAXT];    // tx, ty, tw, th
    __shared__ float2 s_wh[MAXT];    // gw, gh (matched recompute)
    __shared__ int    s_cls[MAXT];
    __shared__ int    s_flag[MAXT];
    __shared__ int    s_nv;
    __shared__ float  s_warp[8];

    if (tid < MAXT) {
        const float* tg = target + b*MAXT*5 + tid*5;
        float t0 = tg[0], t1 = tg[1], t2 = tg[2], t3 = tg[3], t4 = tg[4];
        s_flag[tid] = (t1 != 0.0f) ? 1 : 0;
        float gx = t1 * (float)NW;
        float gy = t2 * (float)NH;
        float gw = t3 * (float)NW;
        float gh = t4 * (float)NH;

        float best = -1.0f; int bn = 0;
        #pragma unroll
        for (int an = 0; an < NA; an++) {
            float iou = wh_iou(gw, gh, c_anchors[2*an], c_anchors[2*an+1]);
            if (iou > best) { best = iou; bn = an; }
        }
        int gi = min(max((int)floorf(gx), 0), NW-1);
        int gj = min(max((int)floorf(gy), 0), NH-1);

        float hw = gw * 0.5f, hh = gh * 0.5f;
        int key = (bn << 12) | (gj << 6) | gi;
        s_bnd[tid] = make_float4(gx - hw, gy - hh, gx + hw, gy + hh);
        s_mk[tid]  = make_float2(0.375f * gw * gh, __int_as_float(key));
        s_wh[tid]  = make_float2(gw, gh);
        s_tv[tid] = make_float4(gx - (float)gi, gy - (float)gj,
                                __logf(fmaxf(gw, 1e-12f) / c_anchors[2*bn]),
                                __logf(fmaxf(gh, 1e-12f) / c_anchors[2*bn+1]));
        s_cls[tid] = (int)t0;
    }
    __syncthreads();
    if (tid == 0) {
        int nv = 0;
        while (nv < MAXT && s_flag[nv]) nv++;
        s_nv = nv;
    }
    __syncthreads();
    int nv = s_nv;

    float aw = c_anchors[2*a], ah = c_anchors[2*a+1];
    const float* base = out + (size_t)(b*NA + a) * CH_PER_A * NCELL;

    // two cells per thread
    int cbase = blockIdx.x * CELLS_PER_BLOCK + tid;
    int cellv[2] = { cbase, cbase + 256 };
    bool act[2]  = { cellv[0] < NCELL, cellv[1] < NCELL };

    float x[2], y[2], conf[2], wr[2], hr[2], pw[2], ph[2];
    float pl[2], pr[2], pt[2], pb[2], q[2];
    int   key[2], mt[2] = { -1, -1 };
    bool  over[2] = { false, false };

    #pragma unroll
    for (int k = 0; k < 2; k++) {
        float xr = 0.f, yr = 0.f, w_ = 0.f, h_ = 0.f, cr = 0.f;
        int cell = act[k] ? cellv[k] : 0;
        if (act[k]) {
            const float* p = base + cell;
            xr = p[0]; yr = p[1*NCELL]; w_ = p[2*NCELL];
            h_ = p[3*NCELL]; cr = p[4*NCELL];
        }
        int j = cell / NW;
        int i = cell - j * NW;
        x[k]    = __fdividef(1.0f, 1.0f + __expf(-xr));
        y[k]    = __fdividef(1.0f, 1.0f + __expf(-yr));
        conf[k] = __fdividef(1.0f, 1.0f + __expf(-cr));
        wr[k] = w_;  hr[k] = h_;
        float px = x[k] + (float)i;
        float py = y[k] + (float)j;
        pw[k] = __expf(w_) * aw;
        ph[k] = __expf(h_) * ah;
        float hw = pw[k] * 0.5f, hh = ph[k] * 0.5f;
        pl[k] = px - hw;  pr[k] = px + hw;
        pt[k] = py - hh;  pb[k] = py + hh;
        q[k]  = 0.375f * pw[k] * ph[k];
        key[k] = act[k] ? ((a << 12) | (j << 6) | i) : -1;
    }

    for (int t = 0; t < nv; t++) {
        float4 bb = s_bnd[t];
        float2 mk = s_mk[t];
        int tkey = __float_as_int(mk.y);
        #pragma unroll
        for (int k = 0; k < 2; k++) {
            float cw = fminf(bb.z, pr[k]) - fmaxf(bb.x, pl[k]);
            float ch = fminf(bb.w, pb[k]) - fmaxf(bb.y, pt[k]);
            float inter = fmaxf(cw, 0.0f) * fmaxf(ch, 0.0f);
            over[k] |= (inter > mk.x + q[k]);          // iou > 0.6
            mt[k] = (tkey == key[k]) ? t : mt[k];      // last match wins
        }
    }

    float lacc = 0.0f;
    #pragma unroll
    for (int k = 0; k < 2; k++) {
        if (!act[k]) continue;
        float txv = 0.5f, tyv = 0.5f, twv = 0.0f, thv = 0.0f, tconf = 0.0f;
        float cm2;
        int m = mt[k];
        if (m >= 0) {
            // exact darknet IoU for the matched target
            float4 bb = s_bnd[m];
            float2 wh = s_wh[m];
            float mx = fminf(bb.x, pl[k]);
            float Mx = fmaxf(bb.z, pr[k]);
            float my = fminf(bb.y, pt[k]);
            float My = fmaxf(bb.w, pb[k]);
            float cw = wh.x + pw[k] - (Mx - mx);
            float ch = wh.y + ph[k] - (My - my);
            float inter = (cw > 0.0f && ch > 0.0f) ? cw*ch : 0.0f;
            float u = wh.x*wh.y + pw[k]*ph[k] - inter;
            tconf = inter / fmaxf(u, 1e-12f);
            float4 tv = s_tv[m];
            txv = tv.x; tyv = tv.y; twv = tv.z; thv = tv.w;
            cm2 = OBJECT_SCALE;
        } else {
            cm2 = over[k] ? 0.0f : 1.0f;
        }

        float dx = x[k] - txv, dy = y[k] - tyv;
        float dw = wr[k] - twv, dh = hr[k] - thv;
        float dc = conf[k] - tconf;
        lacc += 0.5f * (dx*dx + dy*dy + dw*dw + dh*dh + cm2*dc*dc);

        if (m >= 0) {
            int tcls = s_cls[m];
            const float* cp = base + cellv[k] + 5*NCELL;
            float mx = -3.4e38f;
            #pragma unroll 4
            for (int c = 0; c < NC; c++) mx = fmaxf(mx, cp[c*NCELL]);
            float se = 0.0f;
            #pragma unroll 4
            for (int c = 0; c < NC; c++) se += __expf(cp[c*NCELL] - mx);
            lacc -= cp[tcls*NCELL] - mx - __logf(se);
        }
    }

    // block reduction
    #pragma unroll
    for (int o = 16; o > 0; o >>= 1)
        lacc += __shfl_down_sync(0xffffffff, lacc, o);
    if ((tid & 31) == 0) s_warp[tid >> 5] = lacc;
    __syncthreads();
    if (tid == 0) {
        double s = 0.0;
        #pragma unroll
        for (int w = 0; w < 8; w++) s += (double)s_warp[w];
        atomicAdd(&g_acc, s);
        __threadfence();
        unsigned int done = atomicAdd(&g_count, 1u);
        if (done == TOTAL_BLOCKS - 1) {
            res[0] = (float)g_acc;
            g_acc = 0.0;
            g_count = 0;
        }
    }
}

extern "C" void kernel_launch(void* const* d_in, const int* in_sizes, int n_in,
                              void* d_out, int out_size) {
    const float* output = (const float*)d_in[0];
    const float* target = (const float*)d_in[1];
    // d_in[2] = features: never read by the reference loss

    dim3 grid(GRIDX, NB * NA);
    region_loss_k<<<grid, 256>>>(output, target, (float*)d_out);
}